// round 17
// baseline (speedup 1.0000x reference)
#include <cuda_runtime.h>
#include <math.h>

#define NM 1024
#define HH 256
#define WW 256
#define HW 65536
#define OUT_MASKS ((size_t)NM * HW)            // 67108864 floats
#define OUT_KEEP_OFF OUT_MASKS                 // keep[1024]
#define OUT_BOX_OFF (OUT_MASKS + NM)           // boxes[1024*4]

#define IOU_THRESH 0.88f

// ---- scratch (no allocations allowed) ----
__device__ int   g_hi[NM];
__device__ int   g_lo[NM];
__device__ int   g_minr[NM];
__device__ int   g_maxr[NM];
__device__ int   g_minc[NM];
__device__ int   g_maxc[NM];

// ============================================================
// Kernel A — EXACT R4/R11 version (measured 84.6-87.9us @73%
// DRAM, regs=32, occ=90%). Untouchable.
// ============================================================
__global__ void __launch_bounds__(256) sam_fused_kernel(const float* __restrict__ logits,
                                                        const float* __restrict__ iou_preds,
                                                        float* __restrict__ out)
{
    const int tid = threadIdx.x;

    if (blockIdx.x >= NM) {
        // ---- zero-fill path ----
        const int b = blockIdx.x - NM;
        const int n = b >> 2;
        const int q = b & 3;
        if (iou_preds[n] > IOU_THRESH) return;   // handled by kernel B
        float4* __restrict__ o4 = reinterpret_cast<float4*>(out)
                                + (size_t)n * (HW / 4) + (size_t)q * (HW / 16);
        const float4 z = make_float4(0.0f, 0.0f, 0.0f, 0.0f);
#pragma unroll
        for (int it = 0; it < 16; ++it)
            __stcs(&o4[it * 256 + tid], z);
        return;
    }

    // ---- stats path ----
    const int n = blockIdx.x;
    const float4* __restrict__ p =
        reinterpret_cast<const float4*>(logits + (size_t)n * HW);

    int hi = 0, lo = 0;
    int minr = HH, maxr = -1, minc = WW, maxc = -1;

#pragma unroll 8
    for (int it = 0; it < 64; ++it) {
        const int i4 = it * 256 + tid;
        const float4 v = __ldcs(&p[i4]);
        const int e   = i4 << 2;
        const int row = e >> 8;
        const int col = e & 255;

        const float vs0 = v.x, vs1 = v.y, vs2 = v.z, vs3 = v.w;
        hi += (vs0 > 1.0f) + (vs1 > 1.0f) + (vs2 > 1.0f) + (vs3 > 1.0f);
        lo += (vs0 > -1.0f) + (vs1 > -1.0f) + (vs2 > -1.0f) + (vs3 > -1.0f);

        const bool b0 = vs0 > 0.0f, b1 = vs1 > 0.0f, b2 = vs2 > 0.0f, b3 = vs3 > 0.0f;
        if (b0 | b1 | b2 | b3) {
            minr = min(minr, row);
            maxr = max(maxr, row);
            if (b0) { minc = min(minc, col);     maxc = max(maxc, col);     }
            if (b1) { minc = min(minc, col + 1); maxc = max(maxc, col + 1); }
            if (b2) { minc = min(minc, col + 2); maxc = max(maxc, col + 2); }
            if (b3) { minc = min(minc, col + 3); maxc = max(maxc, col + 3); }
        }
    }

#pragma unroll
    for (int o = 16; o > 0; o >>= 1) {
        hi   += __shfl_down_sync(0xFFFFFFFFu, hi, o);
        lo   += __shfl_down_sync(0xFFFFFFFFu, lo, o);
        minr = min(minr, __shfl_down_sync(0xFFFFFFFFu, minr, o));
        maxr = max(maxr, __shfl_down_sync(0xFFFFFFFFu, maxr, o));
        minc = min(minc, __shfl_down_sync(0xFFFFFFFFu, minc, o));
        maxc = max(maxc, __shfl_down_sync(0xFFFFFFFFu, maxc, o));
    }

    __shared__ int s_hi[8], s_lo[8], s_minr[8], s_maxr[8], s_minc[8], s_maxc[8];
    const int w = tid >> 5;
    if ((tid & 31) == 0) {
        s_hi[w] = hi; s_lo[w] = lo;
        s_minr[w] = minr; s_maxr[w] = maxr;
        s_minc[w] = minc; s_maxc[w] = maxc;
    }
    __syncthreads();
    if (tid == 0) {
#pragma unroll
        for (int k = 1; k < 8; ++k) {
            hi += s_hi[k]; lo += s_lo[k];
            minr = min(minr, s_minr[k]); maxr = max(maxr, s_maxr[k]);
            minc = min(minc, s_minc[k]); maxc = max(maxc, s_maxc[k]);
        }
        g_hi[n] = hi;   g_lo[n] = lo;
        g_minr[n] = minr; g_maxr[n] = maxr;
        g_minc[n] = minc; g_maxc[n] = maxc;
    }
}

// ============================================================
// Kernel B: grid = 1 + 4096, 256 threads.
//  block 0           : redundant NMS -> writes keep + boxes
//  blocks 1..4096    : quarter-tile b-1; iou-fail -> instant
//                      exit (zeroed by A); iou-pass -> redundant
//                      NMS (deterministic), then write tile.
// All NMS-running blocks (~493) fit in one wave (33KB smem ->
// 6 blocks/SM), so redundancy costs max, not sum.
// ============================================================
__global__ void __launch_bounds__(256) sam_nms_out_kernel(const float* __restrict__ logits,
                                                          const float* __restrict__ iou_preds,
                                                          float* __restrict__ out)
{
    const int tid = threadIdx.x;
    const bool writer = (blockIdx.x == 0);
    const int b = (int)blockIdx.x - 1;
    const int n = b >> 2;           // tile's mask (garbage for writer; unused)
    const int q = b & 3;

    if (!writer && iou_preds[n] <= IOU_THRESH) return;  // zeroed by A

    // ---- private NMS state (~33KB) ----
    __shared__ float s_key[NM];
    __shared__ int   s_idx[NM];
    __shared__ float s_sl[NM], s_st[NM], s_sr[NM], s_sb[NM];
    __shared__ float s_sa[NM];
    __shared__ float s_gated[NM];
    __shared__ unsigned char s_keep[NM];
    __shared__ int   s_nv;

    if (tid == 0) s_nv = 0;
    __syncthreads();

    float my_sc[4], my_bl[4], my_bt[4], my_br[4], my_bb[4];
    int   my_rank[4];
    bool  my_valid[4];
#pragma unroll
    for (int k = 0; k < 4; ++k) {
        const int m = tid + k * 256;
        const float sc = iou_preds[m];
        const float fhi = (float)g_hi[m];
        const float flo = (float)g_lo[m];
        const float stability = fhi / fmaxf(flo, 1.0f);
        const int mr0 = g_minr[m], mr1 = g_maxr[m];
        const int mc0 = g_minc[m], mc1 = g_maxc[m];
        const bool empty = (mr1 < 0);
        my_sc[k] = sc;
        my_bl[k] = empty ? 0.0f : (float)mc0;
        my_bt[k] = empty ? 0.0f : (float)mr0;
        my_br[k] = empty ? 0.0f : (float)mc1;
        my_bb[k] = empty ? 0.0f : (float)mr1;
        my_valid[k] = (sc > IOU_THRESH) && (stability >= 0.95f);
        if (my_valid[k]) {
            const int pos = atomicAdd(&s_nv, 1);
            s_key[pos] = sc;
            s_idx[pos] = tid + k * 256;
        }
    }
    __syncthreads();
    const int nvalid = s_nv;

    // canonical stable rank (score desc, orig idx asc) + scatter:
    // rank is independent of compaction order -> identical across blocks
#pragma unroll
    for (int k = 0; k < 4; ++k) {
        my_rank[k] = -1;
        if (!my_valid[k]) continue;
        const float sc = my_sc[k];
        const int   m  = tid + k * 256;
        int rank = 0;
        for (int i = 0; i < nvalid; ++i) {
            const float kk = s_key[i];
            rank += (kk > sc) || ((kk == sc) && (s_idx[i] < m));
        }
        my_rank[k] = rank;
        s_sl[rank] = my_bl[k]; s_st[rank] = my_bt[k];
        s_sr[rank] = my_br[k]; s_sb[rank] = my_bb[k];
        s_sa[rank] = fmaxf(my_br[k] - my_bl[k], 0.0f) * fmaxf(my_bb[k] - my_bt[k], 0.0f);
    }
    __syncthreads();

    // warp 0: predicated greedy NMS (uniform inner trip count)
    if (tid < 32) {
        const int lane = tid;
        const int nslot = (nvalid + 31) >> 5;
        unsigned alive = 0;
        for (int t = 0; t < nslot; ++t)
            if (lane + (t << 5) < nvalid) alive |= (1u << t);

        for (int i = 0; i < nvalid; ++i) {
            const unsigned oa = __shfl_sync(0xFFFFFFFFu, alive, i & 31);
            if ((oa >> (i >> 5)) & 1) {                 // warp-uniform test
                const float il = s_sl[i], it_ = s_st[i];
                const float ir = s_sr[i], ib = s_sb[i];
                const float areaI = s_sa[i];
                for (int t = 0; t < nslot; ++t) {
                    const int jj = lane + (t << 5);
                    const bool act = (jj > i) && (jj < nvalid) && ((alive >> t) & 1);
                    const float tl = s_sl[jj], tt = s_st[jj];
                    const float tr = s_sr[jj], tb = s_sb[jj];
                    const float x0 = fmaxf(il, tl), y0 = fmaxf(it_, tt);
                    const float x1 = fminf(ir, tr), y1 = fminf(ib, tb);
                    const float inter = fmaxf(x1 - x0, 0.0f) * fmaxf(y1 - y0, 0.0f);
                    const float uni = fmaxf(areaI + s_sa[jj] - inter, 1e-6f);
                    if (act && (inter / uni > 0.7f)) alive &= ~(1u << t);
                }
            }
        }
        for (int t = 0; t < nslot; ++t) {
            const int jj = lane + (t << 5);
            if (jj < nvalid) s_keep[jj] = (alive >> t) & 1;
        }
    }
    __syncthreads();

    // each thread finalizes gated for its own 4 masks (no atomics)
#pragma unroll
    for (int k = 0; k < 4; ++k) {
        const int m = tid + k * 256;
        const bool kept = my_valid[k] && (s_keep[my_rank[k]] != 0);
        s_gated[m] = kept ? my_sc[k] : 0.0f;
    }
    __syncthreads();

    if (writer) {
        // keep + boxes for all 1024 masks
#pragma unroll
        for (int k = 0; k < 4; ++k) {
            const int m = tid + k * 256;
            out[OUT_KEEP_OFF + m] = (s_gated[m] != 0.0f) ? 1.0f : 0.0f;
            float* ob = out + OUT_BOX_OFF + (size_t)m * 4;
            ob[0] = my_bl[k]; ob[1] = my_bt[k]; ob[2] = my_br[k]; ob[3] = my_bb[k];
        }
        return;
    }

    // ---- write my quarter tile (batched loads, MLP=8) ----
    const float g = s_gated[n];
    const size_t base4 = (size_t)n * (HW / 4) + (size_t)q * (HW / 16);
    float4* __restrict__ o4 = reinterpret_cast<float4*>(out) + base4;

    if (g == 0.0f) {
        const float4 z = make_float4(0.0f, 0.0f, 0.0f, 0.0f);
#pragma unroll
        for (int it = 0; it < 16; ++it)
            __stcs(&o4[it * 256 + tid], z);
    } else {
        const float4* __restrict__ in4 = reinterpret_cast<const float4*>(logits) + base4;
#pragma unroll
        for (int half = 0; half < 2; ++half) {
            float4 v[8];
#pragma unroll
            for (int it = 0; it < 8; ++it)      // 8 loads in flight
                v[it] = __ldcs(&in4[(half * 8 + it) * 256 + tid]);
#pragma unroll
            for (int it = 0; it < 8; ++it) {
                float4 r;
                r.x = g / (1.0f + __expf(-v[it].x));
                r.y = g / (1.0f + __expf(-v[it].y));
                r.z = g / (1.0f + __expf(-v[it].z));
                r.w = g / (1.0f + __expf(-v[it].w));
                __stcs(&o4[(half * 8 + it) * 256 + tid], r);
            }
        }
    }
}

extern "C" void kernel_launch(void* const* d_in, const int* in_sizes, int n_in,
                              void* d_out, int out_size)
{
    const float* logits    = (const float*)d_in[0];  // [1024,256,256]
    const float* iou_preds = (const float*)d_in[1];  // [1024]
    float* out = (float*)d_out;

    sam_fused_kernel<<<NM + NM * 4, 256>>>(logits, iou_preds, out);
    sam_nms_out_kernel<<<1 + NM * 4, 256>>>(logits, iou_preds, out);
}